// round 1
// baseline (speedup 1.0000x reference)
#include <cuda_runtime.h>
#include <cuda_bf16.h>

// PairwiseMax: B=4096, D1=256, D2=256, F=128
// out[b, 0:256]   = x0[b,i] >= 0 ? x0[b,i]*max(x1[b,:]) : x0[b,i]*min(x1[b,:])
// out[b, 256:384] = x2[b,:]
//
// Warp-per-row, float4 everywhere, no shared memory, no block barriers.

#define B_ROWS 4096
#define D1 256
#define D2 256
#define F 128
#define OUT_COLS (D1 + F)          // 384 floats = 96 float4
#define WARPS_PER_BLOCK 8
#define THREADS (WARPS_PER_BLOCK * 32)

__global__ __launch_bounds__(THREADS) void pairwise_max_kernel(
    const float4* __restrict__ x0v,   // [B, 64] float4
    const float4* __restrict__ x1v,   // [B, 64] float4
    const float4* __restrict__ x2v,   // [B, 32] float4
    float4* __restrict__ outv)        // [B, 96] float4
{
    const int warp_id = threadIdx.x >> 5;
    const int lane    = threadIdx.x & 31;
    const int row     = blockIdx.x * WARPS_PER_BLOCK + warp_id;
    if (row >= B_ROWS) return;

    // ---- Phase 1: row max/min of x1 (256 floats = 64 float4; 2 per lane) ----
    const float4* x1row = x1v + (size_t)row * 64;
    float4 a = x1row[lane];
    float4 b = x1row[lane + 32];

    float mx = fmaxf(fmaxf(fmaxf(a.x, a.y), fmaxf(a.z, a.w)),
                     fmaxf(fmaxf(b.x, b.y), fmaxf(b.z, b.w)));
    float mn = fminf(fminf(fminf(a.x, a.y), fminf(a.z, a.w)),
                     fminf(fminf(b.x, b.y), fminf(b.z, b.w)));

    #pragma unroll
    for (int off = 16; off > 0; off >>= 1) {
        mx = fmaxf(mx, __shfl_xor_sync(0xFFFFFFFFu, mx, off));
        mn = fminf(mn, __shfl_xor_sync(0xFFFFFFFFu, mn, off));
    }

    // ---- Phase 2: compute maxes from x0 and write; copy x2 ----
    const float4* x0row  = x0v + (size_t)row * 64;
    const float4* x2row  = x2v + (size_t)row * 32;
    float4*       outrow = outv + (size_t)row * 96;

    float4 c = x0row[lane];
    float4 d = x0row[lane + 32];
    float4 e = x2row[lane];

    float4 oc, od;
    oc.x = c.x * (c.x >= 0.0f ? mx : mn);
    oc.y = c.y * (c.y >= 0.0f ? mx : mn);
    oc.z = c.z * (c.z >= 0.0f ? mx : mn);
    oc.w = c.w * (c.w >= 0.0f ? mx : mn);
    od.x = d.x * (d.x >= 0.0f ? mx : mn);
    od.y = d.y * (d.y >= 0.0f ? mx : mn);
    od.z = d.z * (d.z >= 0.0f ? mx : mn);
    od.w = d.w * (d.w >= 0.0f ? mx : mn);

    outrow[lane]      = oc;
    outrow[lane + 32] = od;
    outrow[lane + 64] = e;   // x2 passthrough
}

extern "C" void kernel_launch(void* const* d_in, const int* in_sizes, int n_in,
                              void* d_out, int out_size)
{
    const float4* x0v = (const float4*)d_in[0];
    const float4* x1v = (const float4*)d_in[1];
    const float4* x2v = (const float4*)d_in[2];
    float4* outv = (float4*)d_out;

    const int blocks = B_ROWS / WARPS_PER_BLOCK;   // 512
    pairwise_max_kernel<<<blocks, THREADS>>>(x0v, x1v, x2v, outv);
}

// round 3
// speedup vs baseline: 1.0739x; 1.0739x over previous
#include <cuda_runtime.h>
#include <cuda_bf16.h>

// PairwiseMax: B=4096, D1=256, D2=256, F=128
// out[b, 0:256]   = x0[b,i] >= 0 ? x0[b,i]*max(x1[b,:]) : x0[b,i]*min(x1[b,:])
// out[b, 256:384] = x2[b,:]
//
// R3: R2 structure (split grid: main rows + dedicated x2 copy blocks,
// front-batched loads) with portable shuffle butterfly (redux.f32 is
// rejected by the harness's ptxas target).

#define B_ROWS 4096
#define WARPS_PER_BLOCK 8
#define THREADS (WARPS_PER_BLOCK * 32)
#define MAIN_BLOCKS (B_ROWS / WARPS_PER_BLOCK)   // 512
#define COPY_BLOCKS 128
#define TOTAL_BLOCKS (MAIN_BLOCKS + COPY_BLOCKS) // 640

// x2 copy geometry: 4096 rows * 32 float4 = 131072 float4 total
#define X2_F4_TOTAL (B_ROWS * 32)
#define COPY_THREADS_TOTAL (COPY_BLOCKS * THREADS)           // 32768
#define F4_PER_COPY_THREAD (X2_F4_TOTAL / COPY_THREADS_TOTAL) // 4

__global__ __launch_bounds__(THREADS) void pairwise_max_kernel(
    const float4* __restrict__ x0v,   // [B, 64] float4
    const float4* __restrict__ x1v,   // [B, 64] float4
    const float4* __restrict__ x2v,   // [B, 32] float4
    float4* __restrict__ outv)        // [B, 96] float4
{
    if (blockIdx.x < MAIN_BLOCKS) {
        // ---------------- main path: x0 / x1 ----------------
        const int warp_id = threadIdx.x >> 5;
        const int lane    = threadIdx.x & 31;
        const int row     = blockIdx.x * WARPS_PER_BLOCK + warp_id;

        const float4* x1row  = x1v + (size_t)row * 64;
        const float4* x0row  = x0v + (size_t)row * 64;
        float4*       outrow = outv + (size_t)row * 96;

        // Front-batch all 4 loads: x0 latency hides under the reduction.
        float4 a = x1row[lane];
        float4 b = x1row[lane + 32];
        float4 c = x0row[lane];
        float4 d = x0row[lane + 32];

        float mx = fmaxf(fmaxf(fmaxf(a.x, a.y), fmaxf(a.z, a.w)),
                         fmaxf(fmaxf(b.x, b.y), fmaxf(b.z, b.w)));
        float mn = fminf(fminf(fminf(a.x, a.y), fminf(a.z, a.w)),
                         fminf(fminf(b.x, b.y), fminf(b.z, b.w)));

        // Two independent shuffle chains interleave in the pipeline.
        #pragma unroll
        for (int off = 16; off > 0; off >>= 1) {
            mx = fmaxf(mx, __shfl_xor_sync(0xFFFFFFFFu, mx, off));
            mn = fminf(mn, __shfl_xor_sync(0xFFFFFFFFu, mn, off));
        }

        float4 oc, od;
        oc.x = c.x * (c.x >= 0.0f ? mx : mn);
        oc.y = c.y * (c.y >= 0.0f ? mx : mn);
        oc.z = c.z * (c.z >= 0.0f ? mx : mn);
        oc.w = c.w * (c.w >= 0.0f ? mx : mn);
        od.x = d.x * (d.x >= 0.0f ? mx : mn);
        od.y = d.y * (d.y >= 0.0f ? mx : mn);
        od.z = d.z * (d.z >= 0.0f ? mx : mn);
        od.w = d.w * (d.w >= 0.0f ? mx : mn);

        outrow[lane]      = oc;
        outrow[lane + 32] = od;
    } else {
        // ---------------- copy path: x2 -> out[:, 256:384] ----------------
        const int t = (blockIdx.x - MAIN_BLOCKS) * THREADS + threadIdx.x;

        #pragma unroll
        for (int i = 0; i < F4_PER_COPY_THREAD; i++) {
            const int idx = t + i * COPY_THREADS_TOTAL;   // coalesced
            const int row = idx >> 5;         // /32 (32 float4 per x2 row)
            const int col = idx & 31;
            outv[(size_t)row * 96 + 64 + col] = x2v[idx];
        }
    }
}

extern "C" void kernel_launch(void* const* d_in, const int* in_sizes, int n_in,
                              void* d_out, int out_size)
{
    const float4* x0v = (const float4*)d_in[0];
    const float4* x1v = (const float4*)d_in[1];
    const float4* x2v = (const float4*)d_in[2];
    float4* outv = (float4*)d_out;

    pairwise_max_kernel<<<TOTAL_BLOCKS, THREADS>>>(x0v, x1v, x2v, outv);
}